// round 5
// baseline (speedup 1.0000x reference)
#include <cuda_runtime.h>
#include <cstdint>

#define T16  16
#define NTAG 50
#define SPIN_MAX (1 << 24)     // bounded spins: any logic bug -> wrong answer, never a hang
#define MBWAIT_MAX 200000

// ---------------- device scratch (no allocations allowed) ----------------
__device__ __align__(16) float g_xb[16 * 1024];   // [t][gate-row] x-part + bias
__device__ __align__(16) float g_charh[256];      // final char hidden
__device__ __align__(16) float g_hword[512];      // word LSTM hidden
__device__ int g_xbcnt = 0;
__device__ int g_chcnt = 0;
__device__ int g_wcnt  = 0;

__device__ __forceinline__ float sigf(float x)  { return __fdividef(1.f, 1.f + __expf(-x)); }
__device__ __forceinline__ float tanh_(float x) { return __fdividef(2.f, 1.f + __expf(-2.f * x)) - 1.f; }

// bounded mbarrier parity wait with cluster-scope acquire
__device__ __forceinline__ void mb_wait(uint32_t mb, uint32_t ph) {
    uint32_t done = 0;
    int it = 0;
    while (!done && it++ < MBWAIT_MAX) {
        asm volatile(
            "{\n\t.reg .pred p;\n\t"
            "mbarrier.try_wait.parity.acquire.cluster.shared::cta.b64 p, [%1], %2, 0x989680;\n\t"
            "selp.b32 %0, 1, 0, p;\n\t}"
            : "=r"(done) : "r"(mb), "r"(ph) : "memory");
    }
}

// =====================================================================
// Single fused kernel. Grid 64 x 256, clusters of 8.
//   CTAs 0-7  (cluster 0): char LSTM, warp-local gates, mbarrier ping-pong sync
//   CTAs 8-63 : xb prep -> word LSTM (phase-2 weights preloaded to regs)
//               -> elected tag head (tagw L2-prefetched during overlap)
// =====================================================================
__global__ void __cluster_dims__(8, 1, 1) __launch_bounds__(256, 1)
fused(const int* __restrict__ wseq, const int* __restrict__ cseq,
      const float* __restrict__ word_emb, const float* __restrict__ char_emb,
      const float* __restrict__ cwih, const float* __restrict__ cwhh,
      const float* __restrict__ cbih, const float* __restrict__ cbhh,
      const float* __restrict__ wwih, const float* __restrict__ wbih,
      const float* __restrict__ wbhh, const float* __restrict__ tagw,
      const float* __restrict__ tagb, float* __restrict__ out)
{
    __shared__ __align__(16) float smem[4352];
    __shared__ __align__(8) unsigned long long mbar[2];
    __shared__ int cs_s[16];
    __shared__ int flag;

    const int tid  = threadIdx.x;
    const int bx   = blockIdx.x;
    const int lane = tid & 31;
    const int w    = tid >> 5;

    // =================================================================
    // cluster 0: char LSTM
    // =================================================================
    if (bx < 8) {
        float* h0 = smem;          // 256
        float* h1 = smem + 256;    // 256
        float* xb = smem + 512;    // 2048
        const int rank  = bx;
        const int jj    = lane >> 3;        // 0..3: j-group within warp
        const int sub   = lane & 7;         // 0..7 within group
        const int gate  = sub >> 1;         // 0=i 1=f 2=g 3=o
        const int halfk = sub & 1;          // which 128 of the 256-dot
        const int jloc  = (w << 2) + jj;    // 0..31
        const int jglob = (rank << 5) + jloc;
        const int wrow  = (gate << 8) + jglob;

        // ---- weight row chunk -> 128 floats in regs as f32x2 pairs ----
        unsigned long long w2[64];
        {
            const ulonglong2* wsrc =
                (const ulonglong2*)(cwhh + (size_t)wrow * 256 + (halfk << 7));
#pragma unroll
            for (int k = 0; k < 32; k++) {
                ulonglong2 v = __ldg(wsrc + k);
                w2[2 * k] = v.x; w2[2 * k + 1] = v.y;
            }
        }
        h0[tid] = 0.f;
        if (tid == 0) {
            uint32_t m0 = (uint32_t)__cvta_generic_to_shared(&mbar[0]);
            uint32_t m1 = (uint32_t)__cvta_generic_to_shared(&mbar[1]);
            asm volatile("mbarrier.init.shared.b64 [%0], %1;" :: "r"(m0), "r"(64u) : "memory");
            asm volatile("mbarrier.init.shared.b64 [%0], %1;" :: "r"(m1), "r"(64u) : "memory");
        }

        // ---- remote addresses (used by lanes 0-7) ----
        uint32_t rh0, rh1, rmb0, rmb1;
        {
            int tgt = lane & 7;
            uint32_t a0 = (uint32_t)__cvta_generic_to_shared(&h0[(rank << 5) + (w << 2)]);
            uint32_t a1 = (uint32_t)__cvta_generic_to_shared(&h1[(rank << 5) + (w << 2)]);
            uint32_t m0 = (uint32_t)__cvta_generic_to_shared(&mbar[0]);
            uint32_t m1 = (uint32_t)__cvta_generic_to_shared(&mbar[1]);
            asm("mapa.shared::cluster.u32 %0,%1,%2;" : "=r"(rh0)  : "r"(a0), "r"(tgt));
            asm("mapa.shared::cluster.u32 %0,%1,%2;" : "=r"(rh1)  : "r"(a1), "r"(tgt));
            asm("mapa.shared::cluster.u32 %0,%1,%2;" : "=r"(rmb0) : "r"(m0), "r"(tgt));
            asm("mapa.shared::cluster.u32 %0,%1,%2;" : "=r"(rmb1) : "r"(m1), "r"(tgt));
        }

        // all cluster CTAs: mbarrier init + h0 zero visible before any traffic
        asm volatile("barrier.cluster.arrive.aligned;" ::: "memory");
        asm volatile("barrier.cluster.wait.aligned;"   ::: "memory");

        // ---- wait (bounded) for xb from prep CTAs, then stage slice ----
        if (tid == 0) {
            int it = 0;
            while (*(volatile int*)&g_xbcnt < 56 && it++ < SPIN_MAX) __nanosleep(64);
            __threadfence();
        }
        __syncthreads();
        for (int i = tid; i < 2048; i += 256) {
            int t = i >> 7, l = i & 127;
            xb[i] = g_xb[(t << 10) + ((l >> 5) << 8) + (rank << 5) + (l & 31)];
        }
        __syncthreads();

        float c = 0.f;
#pragma unroll 1
        for (int t = 0; t < T16; t++) {
            const float* hp = (t & 1) ? h1 : h0;
            float xbv = xb[(t << 7) + (gate << 5) + jloc];
            // ---- 128-element dot, 4 accumulator chains of f32x2 ----
            unsigned long long a0 = 0ull, a1 = 0ull, b0 = 0ull, b1 = 0ull;
            const ulonglong2* h2 = (const ulonglong2*)(hp + (halfk << 7));
#pragma unroll
            for (int k = 0; k < 16; k++) {
                ulonglong2 hva = h2[2 * k], hvb = h2[2 * k + 1];
                asm("fma.rn.f32x2 %0,%1,%2,%0;" : "+l"(a0) : "l"(w2[4 * k + 0]), "l"(hva.x));
                asm("fma.rn.f32x2 %0,%1,%2,%0;" : "+l"(b0) : "l"(w2[4 * k + 1]), "l"(hva.y));
                asm("fma.rn.f32x2 %0,%1,%2,%0;" : "+l"(a1) : "l"(w2[4 * k + 2]), "l"(hvb.x));
                asm("fma.rn.f32x2 %0,%1,%2,%0;" : "+l"(b1) : "l"(w2[4 * k + 3]), "l"(hvb.y));
            }
            float s0, s1, s2, s3, s4, s5, s6, s7;
            asm("mov.b64 {%0,%1},%2;" : "=f"(s0), "=f"(s1) : "l"(a0));
            asm("mov.b64 {%0,%1},%2;" : "=f"(s2), "=f"(s3) : "l"(b0));
            asm("mov.b64 {%0,%1},%2;" : "=f"(s4), "=f"(s5) : "l"(a1));
            asm("mov.b64 {%0,%1},%2;" : "=f"(s6), "=f"(s7) : "l"(b1));
            float v = ((s0 + s2) + (s1 + s3)) + ((s4 + s6) + (s5 + s7));
            v += __shfl_xor_sync(0xffffffffu, v, 1);     // combine the two 128-halves
            v += xbv;
            float act = (gate == 2) ? tanh_(v) : sigf(v);
            // gather the 4 gates of this j (group base = lane & 24)
            int base = lane & 24;
            float iv = __shfl_sync(0xffffffffu, act, base + 0);
            float fv = __shfl_sync(0xffffffffu, act, base + 2);
            float gv = __shfl_sync(0xffffffffu, act, base + 4);
            float ov = __shfl_sync(0xffffffffu, act, base + 6);
            c = fmaf(fv, c, iv * gv);
            float h = ov * tanh_(c);

            if (t < 15) {
                // lane l<8 delivers this warp's 4 h values to CTA l
                float q0 = __shfl_sync(0xffffffffu, h,  0 + sub);
                float q1 = __shfl_sync(0xffffffffu, h,  8 + sub);
                float q2 = __shfl_sync(0xffffffffu, h, 16 + sub);
                float q3 = __shfl_sync(0xffffffffu, h, 24 + sub);
                if (lane < 8) {
                    uint32_t ra = (t & 1) ? rh0 : rh1;    // even t writes h1
                    asm volatile("st.shared::cluster.v4.f32 [%0], {%1,%2,%3,%4};"
                                 :: "r"(ra), "f"(q0), "f"(q1), "f"(q2), "f"(q3) : "memory");
                    uint32_t rm = (t & 1) ? rmb1 : rmb0;  // even t -> mbar[0]
                    asm volatile("mbarrier.arrive.release.cluster.shared::cluster.b64 _, [%0];"
                                 :: "r"(rm) : "memory");
                }
                uint32_t mloc = (uint32_t)__cvta_generic_to_shared(&mbar[t & 1]);
                mb_wait(mloc, (uint32_t)((t >> 1) & 1));
            } else {
                if (sub == 0) { g_charh[jglob] = h; __threadfence(); }
            }
        }
        __syncthreads();
        if (tid == 0) atomicAdd(&g_chcnt, 1);   // target 8
        return;
    }

    // =================================================================
    // CTAs 8-63: xb prep, then word LSTM, then elected tag head
    // =================================================================
    float* ce    = smem;          // 16*132
    float* ws    = smem + 2112;   // 16*132
    float* logit = smem + 4224;   // 64

    const int c0 = bx - 8;        // 0..55

    if (tid == 0) flag = 0;
    if (tid < 16) cs_s[tid] = cseq[tid];
    __syncthreads();

    // stage char embeddings for all 16 timesteps (float4)
    for (int i = tid; i < 512; i += 256) {
        int r = i >> 5, q = i & 31;
        *(float4*)(ce + r * 132 + 4 * q) =
            __ldg((const float4*)(char_emb + (size_t)cs_s[r] * 128) + q);
    }

    // ---- xb chunks: primary c0; CTAs 8-15 also take c0+56 ----
    const int nch = (c0 < 8) ? 2 : 1;
    for (int p = 0; p < nch; p++) {
        int ch = (p == 0) ? c0 : c0 + 56;
        int rbase = ch * 16;
        for (int i = tid; i < 512; i += 256) {
            int r = i >> 5, q = i & 31;
            *(float4*)(ws + r * 132 + 4 * q) =
                __ldg((const float4*)(cwih + (size_t)(rbase + r) * 128) + q);
        }
        __syncthreads();
        {
            int t = tid >> 4, r = tid & 15;
            const float4* w4 = (const float4*)(ws + r * 132);
            const float4* c4 = (const float4*)(ce + t * 132);
            float acc = 0.f;
#pragma unroll
            for (int k = 0; k < 32; k++) {
                float4 a = w4[k], b = c4[k];
                acc = fmaf(a.x, b.x, acc); acc = fmaf(a.y, b.y, acc);
                acc = fmaf(a.z, b.z, acc); acc = fmaf(a.w, b.w, acc);
            }
            int grow = rbase + r;
            g_xb[t * 1024 + grow] = acc + cbih[grow] + cbhh[grow];
        }
        __syncthreads();
    }
    if (tid == 0) { __threadfence(); atomicAdd(&g_xbcnt, 1); }   // target 56

    // ---- word LSTM: warp per output j; jobs wg and (wg<64 ? wg+448) ----
    const int wg = c0 * 8 + w;    // 0..447
    int jl[2]; int nj = 1;
    jl[0] = wg;
    if (wg < 64) { jl[1] = wg + 448; nj = 2; }

    const int widx = __ldg(wseq);
    const float4* xwe = (const float4*)(word_emb + (size_t)widx * 512);  // 128 f4

    // phase 1 (cols [0,512)) + prefetch phase-2 weights & biases to regs
    float  p1[2][3];
    float4 p2w[2][6];    // [job][gate*2 + chunk]
    float  pb[2][3];
#pragma unroll
    for (int p = 0; p < 2; p++) {
        if (p >= nj) break;
        int j = jl[p];
        const float4* ri = (const float4*)wwih + (size_t)j * 192;
        const float4* rg = (const float4*)wwih + (size_t)(1024 + j) * 192;
        const float4* ro = (const float4*)wwih + (size_t)(1536 + j) * 192;
        float ai = 0.f, ag = 0.f, ao = 0.f;
#pragma unroll
        for (int cc = 0; cc < 4; cc++) {
            int idx = cc * 32 + lane;
            float4 x = xwe[idx];
            float4 a = __ldg(ri + idx), b = __ldg(rg + idx), d = __ldg(ro + idx);
            ai = fmaf(a.x, x.x, ai); ai = fmaf(a.y, x.y, ai);
            ai = fmaf(a.z, x.z, ai); ai = fmaf(a.w, x.w, ai);
            ag = fmaf(b.x, x.x, ag); ag = fmaf(b.y, x.y, ag);
            ag = fmaf(b.z, x.z, ag); ag = fmaf(b.w, x.w, ag);
            ao = fmaf(d.x, x.x, ao); ao = fmaf(d.y, x.y, ao);
            ao = fmaf(d.z, x.z, ao); ao = fmaf(d.w, x.w, ao);
        }
        p1[p][0] = ai; p1[p][1] = ag; p1[p][2] = ao;
#pragma unroll
        for (int cc = 0; cc < 2; cc++) {
            int idx = (4 + cc) * 32 + lane;
            p2w[p][0 * 2 + cc] = __ldg(ri + idx);
            p2w[p][1 * 2 + cc] = __ldg(rg + idx);
            p2w[p][2 * 2 + cc] = __ldg(ro + idx);
        }
        pb[p][0] = __ldg(wbih + j)        + __ldg(wbhh + j);
        pb[p][1] = __ldg(wbih + 1024 + j) + __ldg(wbhh + 1024 + j);
        pb[p][2] = __ldg(wbih + 1536 + j) + __ldg(wbhh + 1536 + j);
    }

    // L2-prefetch tag weights during the overlap window (CTA 63 only)
    if (c0 == 55) {
        const char* tp = (const char*)tagw;
        for (int off = tid * 128; off < NTAG * 512 * 4; off += 256 * 128)
            asm volatile("prefetch.global.L2 [%0];" :: "l"(tp + off));
        if (tid == 0) asm volatile("prefetch.global.L2 [%0];" :: "l"((const char*)tagb));
    }

    // wait (bounded) for char hidden
    if (lane == 0) {
        int it = 0;
        while (*(volatile int*)&g_chcnt < 8 && it++ < SPIN_MAX) __nanosleep(32);
    }
    __syncwarp();
    __threadfence();

    // phase 2: cols [512,768) against g_charh from preloaded regs
    const float4* ch4 = (const float4*)g_charh;   // 64 f4
#pragma unroll
    for (int p = 0; p < 2; p++) {
        if (p >= nj) break;
        int j = jl[p];
        float ai = p1[p][0], ag = p1[p][1], ao = p1[p][2];
#pragma unroll
        for (int cc = 0; cc < 2; cc++) {
            float4 x = ch4[cc * 32 + lane];
            float4 a = p2w[p][0 * 2 + cc], b = p2w[p][1 * 2 + cc], d = p2w[p][2 * 2 + cc];
            ai = fmaf(a.x, x.x, ai); ai = fmaf(a.y, x.y, ai);
            ai = fmaf(a.z, x.z, ai); ai = fmaf(a.w, x.w, ai);
            ag = fmaf(b.x, x.x, ag); ag = fmaf(b.y, x.y, ag);
            ag = fmaf(b.z, x.z, ag); ag = fmaf(b.w, x.w, ag);
            ao = fmaf(d.x, x.x, ao); ao = fmaf(d.y, x.y, ao);
            ao = fmaf(d.z, x.z, ao); ao = fmaf(d.w, x.w, ao);
        }
#pragma unroll
        for (int s = 16; s; s >>= 1) {
            ai += __shfl_xor_sync(0xffffffffu, ai, s);
            ag += __shfl_xor_sync(0xffffffffu, ag, s);
            ao += __shfl_xor_sync(0xffffffffu, ao, s);
        }
        if (lane == 0) {
            float iv = sigf(ai + pb[p][0]);
            float gv = tanh_(ag + pb[p][1]);
            float ov = sigf(ao + pb[p][2]);
            g_hword[j] = ov * tanh_(iv * gv);     // c_prev = 0 -> c = i*g
            __threadfence();
            int old = atomicAdd(&g_wcnt, 1);
            if (old == 511) flag = 1;             // last job globally -> this CTA tags
        }
    }
    __syncthreads();
    if (!flag) return;
    __threadfence();

    // ---- tag head + log_softmax (elected CTA only; tagw likely in L2) ----
    const float4* hw4 = (const float4*)g_hword;   // 128 f4
    for (int o = w; o < NTAG; o += 8) {
        const float4* tw = (const float4*)(tagw + (size_t)o * 512);
        float acc = 0.f;
#pragma unroll
        for (int cc = 0; cc < 4; cc++) {
            int idx = cc * 32 + lane;
            float4 a = __ldg(tw + idx), x = hw4[idx];
            acc = fmaf(a.x, x.x, acc); acc = fmaf(a.y, x.y, acc);
            acc = fmaf(a.z, x.z, acc); acc = fmaf(a.w, x.w, acc);
        }
#pragma unroll
        for (int s = 16; s; s >>= 1) acc += __shfl_xor_sync(0xffffffffu, acc, s);
        if (lane == 0) logit[o] = acc + tagb[o];
    }
    __syncthreads();
    if (tid == 0) {
        float m = -1e30f;
        for (int i = 0; i < NTAG; i++) m = fmaxf(m, logit[i]);
        float s = 0.f;
        for (int i = 0; i < NTAG; i++) s += expf(logit[i] - m);
        float ls = logf(s) + m;
        for (int i = 0; i < NTAG; i++) out[i] = logit[i] - ls;
        g_xbcnt = 0; g_chcnt = 0; g_wcnt = 0;     // reset for graph replay
    }
}

// =====================================================================
extern "C" void kernel_launch(void* const* d_in, const int* in_sizes, int n_in,
                              void* d_out, int out_size)
{
    const int*   wseq     = (const int*)  d_in[0];
    const int*   cseq     = (const int*)  d_in[1];
    const float* word_emb = (const float*)d_in[2];
    const float* char_emb = (const float*)d_in[3];
    const float* cwih     = (const float*)d_in[4];
    const float* cwhh     = (const float*)d_in[5];
    const float* cbih     = (const float*)d_in[6];
    const float* cbhh     = (const float*)d_in[7];
    const float* wwih     = (const float*)d_in[8];
    /* d_in[9] = word_w_hh: provably unused (seq len 1, zero initial state) */
    const float* wbih     = (const float*)d_in[10];
    const float* wbhh     = (const float*)d_in[11];
    const float* tagw     = (const float*)d_in[12];
    const float* tagb     = (const float*)d_in[13];
    float* out = (float*)d_out;

    fused<<<64, 256>>>(wseq, cseq, word_emb, char_emb, cwih, cwhh, cbih, cbhh,
                       wwih, wbih, wbhh, tagw, tagb, out);
}